// round 16
// baseline (speedup 1.0000x reference)
#include <cuda_runtime.h>
#include <cuda_fp16.h>
#include <cuda_bf16.h>

#define N_NODES 100000
#define N_EDGES 1600000
#define D 64
#define SCAN_B 1024
#define NB_SCAN ((N_NODES + SCAN_B - 1) / SCAN_B)   // 98

typedef unsigned long long ull;

// Scratch (__device__ globals; zero-initialized at load, each replay restores
// the zeroed-deg invariant itself — no explicit zero kernel needed)
__device__ int     g_deg[N_NODES];
__device__ int     g_off[N_NODES];
__device__ int     g_cursor[N_NODES];
__device__ int     g_bsum[NB_SCAN];
__device__ float   g_dinv[N_NODES];
__device__ int     g_csr[N_EDGES];
__device__ __half2 g_zh[N_NODES * (D / 2)];   // Z = diag(dinv)*(X@W), fp16, 12.8 MB

// ---- packed f32x2 helpers (sm_10x; FFMA2 only reachable via PTX) ----------
__device__ __forceinline__ ull pack2(float lo, float hi) {
    ull r; asm("mov.b64 %0, {%1, %2};" : "=l"(r) : "f"(lo), "f"(hi)); return r;
}
__device__ __forceinline__ ull fma2(ull a, ull b, ull c) {   // a*b + c
    ull d; asm("fma.rn.f32x2 %0, %1, %2, %3;" : "=l"(d) : "l"(a), "l"(b), "l"(c));
    return d;
}
__device__ __forceinline__ ull mul2(ull a, ull b) {
    ull d; asm("mul.rn.f32x2 %0, %1, %2;" : "=l"(d) : "l"(a), "l"(b)); return d;
}
__device__ __forceinline__ unsigned f32x2_to_h2(ull p) {     // packed f32x2 -> half2 bits
    float lo, hi;
    asm("mov.b64 {%0, %1}, %2;" : "=f"(lo), "=f"(hi) : "l"(p));
    __half2 h = __floats2half2_rn(lo, hi);
    return *(unsigned*)&h;
}

// ---------------------------------------------------------------------------
// 1) in-degree histogram by target (int4-vectorized; N_EDGES % 4 == 0)
// ---------------------------------------------------------------------------
__global__ void degree_kernel(const int4* __restrict__ tgt4) {
    int e4 = blockIdx.x * blockDim.x + threadIdx.x;
    if (e4 < N_EDGES / 4) {
        int4 t = tgt4[e4];
        atomicAdd(&g_deg[t.x], 1);
        atomicAdd(&g_deg[t.y], 1);
        atomicAdd(&g_deg[t.z], 1);
        atomicAdd(&g_deg[t.w], 1);
    }
}

// ---------------------------------------------------------------------------
// 2a) per-block exclusive scan of degrees (block sums to g_bsum) + dinv
// ---------------------------------------------------------------------------
__global__ void scan1_kernel() {
    __shared__ int s[SCAN_B];
    int gid = blockIdx.x * SCAN_B + threadIdx.x;
    int v = (gid < N_NODES) ? g_deg[gid] : 0;
    s[threadIdx.x] = v;
    if (gid < N_NODES) g_dinv[gid] = rsqrtf((float)v);
    __syncthreads();
    for (int ofs = 1; ofs < SCAN_B; ofs <<= 1) {
        int t = (threadIdx.x >= ofs) ? s[threadIdx.x - ofs] : 0;
        __syncthreads();
        s[threadIdx.x] += t;
        __syncthreads();
    }
    if (gid < N_NODES) g_off[gid] = s[threadIdx.x] - v;   // exclusive
    if (threadIdx.x == SCAN_B - 1) g_bsum[blockIdx.x] = s[SCAN_B - 1];
}

// ---------------------------------------------------------------------------
// 2b) fixup: add block prefix (reduced locally) + seed cursor with offset
// ---------------------------------------------------------------------------
__global__ void scan3_kernel() {
    __shared__ int red[256];
    int i = blockIdx.x * 256 + threadIdx.x;
    int j = blockIdx.x >> 2;            // owning scan1 block (1024/256 = 4)
    int v = (threadIdx.x < j) ? g_bsum[threadIdx.x] : 0;   // j <= 97 < 256
    red[threadIdx.x] = v;
    __syncthreads();
    #pragma unroll
    for (int ofs = 128; ofs > 0; ofs >>= 1) {
        if (threadIdx.x < ofs) red[threadIdx.x] += red[threadIdx.x + ofs];
        __syncthreads();
    }
    int bpref = red[0];
    if (i < N_NODES) {
        int o = g_off[i] + bpref;
        g_off[i] = o;
        g_cursor[i] = o;                // fill uses cursor directly as slot
    }
}

// ---------------------------------------------------------------------------
// 3) CSR fill: bucket src indices by target (int4-vectorized, 1 atomic each)
// ---------------------------------------------------------------------------
__global__ void fill_kernel(const int4* __restrict__ src4,
                            const int4* __restrict__ tgt4) {
    int e4 = blockIdx.x * blockDim.x + threadIdx.x;
    if (e4 < N_EDGES / 4) {
        int4 s = src4[e4];
        int4 t = tgt4[e4];
        g_csr[atomicAdd(&g_cursor[t.x], 1)] = s.x;
        g_csr[atomicAdd(&g_cursor[t.y], 1)] = s.y;
        g_csr[atomicAdd(&g_cursor[t.z], 1)] = s.z;
        g_csr[atomicAdd(&g_cursor[t.w], 1)] = s.w;
    }
}

// ---------------------------------------------------------------------------
// 4) Z = fp16( diag(dinv) * (X @ W) ). One thread per node, W smem-broadcast,
//    packed f32x2 FFMA, half2 conversion on store.
// ---------------------------------------------------------------------------
__global__ void __launch_bounds__(256) zgemm_kernel(const float* __restrict__ x,
                                                    const float* __restrict__ W) {
    __shared__ float Ws[D * D];      // 16 KB
    int tid = threadIdx.x;
    for (int i = tid; i < D * D; i += 256) Ws[i] = W[i];
    __syncthreads();

    int node = blockIdx.x * 256 + tid;
    if (node >= N_NODES) return;

    ull acc[32];                      // 64 output cols as 32 packed f32x2
    #pragma unroll
    for (int j = 0; j < 32; j++) acc[j] = 0ULL;   // {0.f, 0.f}

    const float4* xr = (const float4*)(x + (size_t)node * D);
    #pragma unroll 2
    for (int k4 = 0; k4 < 16; k4++) {
        float4 xv = xr[k4];
        float xs[4] = {xv.x, xv.y, xv.z, xv.w};
        #pragma unroll
        for (int kk = 0; kk < 4; kk++) {
            ull xk2 = pack2(xs[kk], xs[kk]);
            const ulonglong2* wrow = (const ulonglong2*)&Ws[(k4 * 4 + kk) * D];
            #pragma unroll
            for (int j = 0; j < 16; j++) {
                ulonglong2 w = wrow[j];           // broadcast LDS.128
                acc[2 * j]     = fma2(xk2, w.x, acc[2 * j]);
                acc[2 * j + 1] = fma2(xk2, w.y, acc[2 * j + 1]);
            }
        }
    }

    float dv = g_dinv[node];
    ull dv2 = pack2(dv, dv);
    uint4* zr = (uint4*)(g_zh + (size_t)node * (D / 2));
    #pragma unroll
    for (int q = 0; q < 8; q++) {                  // 8 x STG.128
        uint4 o;
        o.x = f32x2_to_h2(mul2(acc[4 * q + 0], dv2));
        o.y = f32x2_to_h2(mul2(acc[4 * q + 1], dv2));
        o.z = f32x2_to_h2(mul2(acc[4 * q + 2], dv2));
        o.w = f32x2_to_h2(mul2(acc[4 * q + 3], dv2));
        zr[q] = o;
    }
}

// ---------------------------------------------------------------------------
// 5) gather: out[t] = relu(dinv_t * sum_{s in N(t)} Z[s] + b)
//    16 lanes per node (lane c owns 4 halves = 8B), fp32 accumulation.
//    Also resets g_deg for the next graph replay.
// ---------------------------------------------------------------------------
__global__ void __launch_bounds__(256) gather_kernel(const float* __restrict__ b,
                                                     float* __restrict__ out) {
    int tid = threadIdx.x;
    int c = tid & 15;
    int node = blockIdx.x * 16 + (tid >> 4);   // 6250 * 16 = 100000 exactly

    int off = g_off[node];                      // broadcast within segment
    int deg = g_deg[node];
    if (c == 0) g_deg[node] = 0;                // restore zeroed-deg invariant

    const uint2* __restrict__ z2 = (const uint2*)g_zh;   // 16 uint2 per row

    float2 a0 = make_float2(0.f, 0.f);
    float2 a1 = make_float2(0.f, 0.f);
    int i = 0;
    for (; i + 4 <= deg; i += 4) {
        int i0 = g_csr[off + i];
        int i1 = g_csr[off + i + 1];
        int i2 = g_csr[off + i + 2];
        int i3 = g_csr[off + i + 3];
        uint2 v0 = z2[i0 * 16 + c];
        uint2 v1 = z2[i1 * 16 + c];
        uint2 v2 = z2[i2 * 16 + c];
        uint2 v3 = z2[i3 * 16 + c];
        float2 f;
        f = __half22float2(*(__half2*)&v0.x); a0.x += f.x; a0.y += f.y;
        f = __half22float2(*(__half2*)&v0.y); a1.x += f.x; a1.y += f.y;
        f = __half22float2(*(__half2*)&v1.x); a0.x += f.x; a0.y += f.y;
        f = __half22float2(*(__half2*)&v1.y); a1.x += f.x; a1.y += f.y;
        f = __half22float2(*(__half2*)&v2.x); a0.x += f.x; a0.y += f.y;
        f = __half22float2(*(__half2*)&v2.y); a1.x += f.x; a1.y += f.y;
        f = __half22float2(*(__half2*)&v3.x); a0.x += f.x; a0.y += f.y;
        f = __half22float2(*(__half2*)&v3.y); a1.x += f.x; a1.y += f.y;
    }
    for (; i < deg; i++) {
        int i0 = g_csr[off + i];
        uint2 v0 = z2[i0 * 16 + c];
        float2 f;
        f = __half22float2(*(__half2*)&v0.x); a0.x += f.x; a0.y += f.y;
        f = __half22float2(*(__half2*)&v0.y); a1.x += f.x; a1.y += f.y;
    }

    float dn = g_dinv[node];
    float4 bias = ((const float4*)b)[c];
    float4 o;
    o.x = fmaxf(fmaf(a0.x, dn, bias.x), 0.f);
    o.y = fmaxf(fmaf(a0.y, dn, bias.y), 0.f);
    o.z = fmaxf(fmaf(a1.x, dn, bias.z), 0.f);
    o.w = fmaxf(fmaf(a1.y, dn, bias.w), 0.f);
    ((float4*)&out[(size_t)node * D])[c] = o;
}

// ---------------------------------------------------------------------------
// launch (6 kernels)
// ---------------------------------------------------------------------------
extern "C" void kernel_launch(void* const* d_in, const int* in_sizes, int n_in,
                              void* d_out, int out_size) {
    const float* x   = (const float*)d_in[0];   // [N_NODES, 64]
    const float* W   = (const float*)d_in[1];   // [64, 64]
    const float* b   = (const float*)d_in[2];   // [64]
    const int*   src = (const int*)d_in[3];     // [N_EDGES]
    const int*   tgt = (const int*)d_in[4];     // [N_EDGES]
    float* out = (float*)d_out;                 // [N_NODES, 64]

    degree_kernel<<<(N_EDGES / 4 + 255) / 256, 256>>>((const int4*)tgt);
    scan1_kernel<<<NB_SCAN, SCAN_B>>>();
    scan3_kernel<<<(N_NODES + 255) / 256, 256>>>();
    fill_kernel<<<(N_EDGES / 4 + 255) / 256, 256>>>((const int4*)src, (const int4*)tgt);
    zgemm_kernel<<<(N_NODES + 255) / 256, 256>>>(x, W);
    gather_kernel<<<N_NODES / 16, 256>>>(b, out);
}